// round 1
// baseline (speedup 1.0000x reference)
#include <cuda_runtime.h>
#include <cstdint>

using u64 = unsigned long long;

// Packed fp32x2 FMA (Blackwell FFMA2) — 2 MACs per instruction at FFMA issue rate.
__device__ __forceinline__ u64 ffma2(u64 a, u64 b, u64 c) {
    u64 d;
    asm("fma.rn.f32x2 %0, %1, %2, %3;" : "=l"(d) : "l"(a), "l"(b), "l"(c));
    return d;
}
__device__ __forceinline__ u64 dup2(float x) {
    u64 d;
    asm("mov.b64 %0, {%1, %1};" : "=l"(d) : "f"(x));
    return d;
}

// Scratch for t4[m][l][n][c]  (1024 x 14 x 14 x 256 fp32 = 205.5 MB)
__device__ float g_t4[(size_t)1024 * 14 * 14 * 256];

// ---------------------------------------------------------------------------
// k1: t4[m,l,n,c] = sum_{j=0..127, k=0..2} x4[m,j,l,n+k-1] * w2[j,k,c]
//     x4[m,j,l,h] = x[m*25088 + j*196 + l*14 + h], zero-padded in h.
// Block handles (m, l-pair). 128 threads; thread t owns channel pair (2t, 2t+1)
// packed in fp32x2. w2 loads are reused across both l's (halves L2 traffic).
// ---------------------------------------------------------------------------
__global__ __launch_bounds__(128) void k1(const float* __restrict__ x,
                                          const float* __restrict__ w2) {
    __shared__ float xs[2][128][16];   // [l-sub][j][h+1], h pads at 0 and 15

    const int tid = threadIdx.x;
    const int l0  = blockIdx.x * 2;    // l-pair: l0, l0+1   (14 = 7 pairs)
    const int m   = blockIdx.y;

    // zero the h-pads
    xs[0][tid][0] = 0.f; xs[0][tid][15] = 0.f;
    xs[1][tid][0] = 0.f; xs[1][tid][15] = 0.f;

    const float* xm = x + (size_t)m * 25088;
    for (int i = tid; i < 3584; i += 128) {          // 2*128*14 elements, 28 iters
        int lp = i / 1792;
        int r  = i - lp * 1792;
        int j  = r / 14;
        int h  = r - j * 14;
        xs[lp][j][h + 1] = xm[j * 196 + (l0 + lp) * 14 + h];
    }
    __syncthreads();

    u64 acc[2][14];
    #pragma unroll
    for (int a = 0; a < 2; a++)
        #pragma unroll
        for (int n = 0; n < 14; n++) acc[a][n] = 0ull;

    // w2[j][k][c] as fp32x2: index j*384 + k*128 + t
    const u64* __restrict__ w2u = (const u64*)w2 + tid;

    for (int j = 0; j < 128; j++) {
        const u64 wa = w2u[j * 384];         // k = 0
        const u64 wb = w2u[j * 384 + 128];   // k = 1
        const u64 wc = w2u[j * 384 + 256];   // k = 2
        #pragma unroll
        for (int a = 0; a < 2; a++) {
            u64 xd[16];
            #pragma unroll
            for (int h = 0; h < 16; h++) xd[h] = dup2(xs[a][j][h]);
            #pragma unroll
            for (int n = 0; n < 14; n++) {
                acc[a][n] = ffma2(xd[n],     wa, acc[a][n]);  // k=0 -> h = n-1
                acc[a][n] = ffma2(xd[n + 1], wb, acc[a][n]);  // k=1 -> h = n
                acc[a][n] = ffma2(xd[n + 2], wc, acc[a][n]);  // k=2 -> h = n+1
            }
        }
    }

    #pragma unroll
    for (int a = 0; a < 2; a++) {
        u64* o = (u64*)g_t4 + ((size_t)(m * 14 + l0 + a) * 14) * 128 + tid;
        #pragma unroll
        for (int n = 0; n < 14; n++) o[n * 128] = acc[a][n];  // coalesced 8B stores
    }
}

// ---------------------------------------------------------------------------
// k2: out[m,c,aa,b] = w1[c,0]*t4[m,(aa-1)%14,b,c] + w1[c,1]*t4[m,(aa-2)%14,b,c]
// Block per (aa, m); smem-staged transpose (c-major reads -> b-contiguous writes)
// ---------------------------------------------------------------------------
__global__ __launch_bounds__(256) void k2(const float* __restrict__ w1,
                                          float* __restrict__ out) {
    __shared__ float s1[14][257];   // +1 pad kills the stride-256 bank conflict
    __shared__ float s2[14][257];

    const int aa  = blockIdx.x;                // 0..13
    const int m   = blockIdx.y;
    const int l1  = (aa + 13) % 14;            // (aa-1) mod 14
    const int l2  = (aa + 12) % 14;            // (aa-2) mod 14
    const int tid = threadIdx.x;

    const float* t41 = g_t4 + ((size_t)(m * 14 + l1) * 14) * 256;
    const float* t42 = g_t4 + ((size_t)(m * 14 + l2) * 14) * 256;
    for (int i = tid; i < 14 * 256; i += 256) {   // fully coalesced loads
        int b = i >> 8, c = i & 255;
        s1[b][c] = t41[i];
        s2[b][c] = t42[i];
    }
    __syncthreads();

    float* om = out + (size_t)m * 50176 + aa * 14;
    for (int i = tid; i < 14 * 256; i += 256) {
        int c = i / 14, b = i - c * 14;
        float v = w1[2 * c] * s1[b][c] + w1[2 * c + 1] * s2[b][c];
        om[c * 196 + b] = v;                       // 14-float contiguous runs
    }
}

extern "C" void kernel_launch(void* const* d_in, const int* in_sizes, int n_in,
                              void* d_out, int out_size) {
    const float* x  = (const float*)d_in[0];   // (1024, 1792, 14) f32
    const float* w1 = (const float*)d_in[1];   // (256, 2) f32
    const float* w2 = (const float*)d_in[2];   // (128, 3, 256) f32
    float* out = (float*)d_out;                // (1024, 256, 14, 14) f32

    dim3 g1(7, 1024);
    k1<<<g1, 128>>>(x, w2);
    dim3 g2(14, 1024);
    k2<<<g2, 256>>>(w1, out);
}

// round 2
// speedup vs baseline: 1.5237x; 1.5237x over previous
#include <cuda_runtime.h>
#include <cstdint>

using u64 = unsigned long long;

// Packed fp32x2 FMA (Blackwell FFMA2) — 2 MACs per instruction at FFMA issue rate.
__device__ __forceinline__ u64 ffma2(u64 a, u64 b, u64 c) {
    u64 d;
    asm("fma.rn.f32x2 %0, %1, %2, %3;" : "=l"(d) : "l"(a), "l"(b), "l"(c));
    return d;
}
__device__ __forceinline__ u64 dup2(float x) {
    u64 d;
    asm("mov.b64 %0, {%1, %1};" : "=l"(d) : "f"(x));
    return d;
}

// Scratch for t4[m][l][n][c]  (1024 x 14 x 14 x 256 fp32 = 205.5 MB)
__device__ float g_t4[(size_t)1024 * 14 * 14 * 256];

// ---------------------------------------------------------------------------
// k1: t4[m,l,n,c] = sum_{j=0..127, k=0..2} x4[m,j,l,n+k-1] * w2[j,k,c]
//     x4[m,j,l,h] = x[m*25088 + j*196 + l*14 + h], zero-padded in h.
// Block handles (m, l-pair). 128 threads; thread t owns channel pair (2t, 2t+1)
// packed in fp32x2. w2 loads are reused across both l's (halves L2 traffic).
// ---------------------------------------------------------------------------
__global__ __launch_bounds__(128) void k1(const float* __restrict__ x,
                                          const float* __restrict__ w2) {
    __shared__ float xs[2][128][16];   // [l-sub][j][h+1], h pads at 0 and 15

    const int tid = threadIdx.x;
    const int l0  = blockIdx.x * 2;    // l-pair: l0, l0+1   (14 = 7 pairs)
    const int m   = blockIdx.y;

    // zero the h-pads
    xs[0][tid][0] = 0.f; xs[0][tid][15] = 0.f;
    xs[1][tid][0] = 0.f; xs[1][tid][15] = 0.f;

    const float* xm = x + (size_t)m * 25088;
    for (int i = tid; i < 3584; i += 128) {          // 2*128*14 elements, 28 iters
        int lp = i / 1792;
        int r  = i - lp * 1792;
        int j  = r / 14;
        int h  = r - j * 14;
        xs[lp][j][h + 1] = xm[j * 196 + (l0 + lp) * 14 + h];
    }
    __syncthreads();

    u64 acc[2][14];
    #pragma unroll
    for (int a = 0; a < 2; a++)
        #pragma unroll
        for (int n = 0; n < 14; n++) acc[a][n] = 0ull;

    // w2[j][k][c] as fp32x2: index j*384 + k*128 + t
    const u64* __restrict__ w2u = (const u64*)w2 + tid;

    for (int j = 0; j < 128; j++) {
        const u64 wa = w2u[j * 384];         // k = 0
        const u64 wb = w2u[j * 384 + 128];   // k = 1
        const u64 wc = w2u[j * 384 + 256];   // k = 2
        #pragma unroll
        for (int a = 0; a < 2; a++) {
            u64 xd[16];
            #pragma unroll
            for (int h = 0; h < 16; h++) xd[h] = dup2(xs[a][j][h]);
            #pragma unroll
            for (int n = 0; n < 14; n++) {
                acc[a][n] = ffma2(xd[n],     wa, acc[a][n]);  // k=0 -> h = n-1
                acc[a][n] = ffma2(xd[n + 1], wb, acc[a][n]);  // k=1 -> h = n
                acc[a][n] = ffma2(xd[n + 2], wc, acc[a][n]);  // k=2 -> h = n+1
            }
        }
    }

    #pragma unroll
    for (int a = 0; a < 2; a++) {
        u64* o = (u64*)g_t4 + ((size_t)(m * 14 + l0 + a) * 14) * 128 + tid;
        #pragma unroll
        for (int n = 0; n < 14; n++) o[n * 128] = acc[a][n];  // coalesced 8B stores
    }
}

// ---------------------------------------------------------------------------
// k2: out[m,c,aa,b] = w1[c,0]*t4[m,(aa-1)%14,b,c] + w1[c,1]*t4[m,(aa-2)%14,b,c]
// Block per (aa, m); smem-staged transpose (c-major reads -> b-contiguous writes)
// ---------------------------------------------------------------------------
__global__ __launch_bounds__(256) void k2(const float* __restrict__ w1,
                                          float* __restrict__ out) {
    __shared__ float s1[14][257];   // +1 pad kills the stride-256 bank conflict
    __shared__ float s2[14][257];

    const int aa  = blockIdx.x;                // 0..13
    const int m   = blockIdx.y;
    const int l1  = (aa + 13) % 14;            // (aa-1) mod 14
    const int l2  = (aa + 12) % 14;            // (aa-2) mod 14
    const int tid = threadIdx.x;

    const float* t41 = g_t4 + ((size_t)(m * 14 + l1) * 14) * 256;
    const float* t42 = g_t4 + ((size_t)(m * 14 + l2) * 14) * 256;
    for (int i = tid; i < 14 * 256; i += 256) {   // fully coalesced loads
        int b = i >> 8, c = i & 255;
        s1[b][c] = t41[i];
        s2[b][c] = t42[i];
    }
    __syncthreads();

    float* om = out + (size_t)m * 50176 + aa * 14;
    for (int i = tid; i < 14 * 256; i += 256) {
        int c = i / 14, b = i - c * 14;
        float v = w1[2 * c] * s1[b][c] + w1[2 * c + 1] * s2[b][c];
        om[c * 196 + b] = v;                       // 14-float contiguous runs
    }
}

extern "C" void kernel_launch(void* const* d_in, const int* in_sizes, int n_in,
                              void* d_out, int out_size) {
    const float* x  = (const float*)d_in[0];   // (1024, 1792, 14) f32
    const float* w1 = (const float*)d_in[1];   // (256, 2) f32
    const float* w2 = (const float*)d_in[2];   // (128, 3, 256) f32
    float* out = (float*)d_out;                // (1024, 256, 14, 14) f32

    dim3 g1(7, 1024);
    k1<<<g1, 128>>>(x, w2);
    dim3 g2(14, 1024);
    k2<<<g2, 256>>>(w1, out);
}

// round 4
// speedup vs baseline: 5.1445x; 3.3762x over previous
#include <cuda_runtime.h>
#include <cuda_fp16.h>
#include <cstdint>

// ===========================================================================
// Fused kernel: one CTA per m.
//   out[m,c,p,b] = w1[c,0]*t4[l1,b,c] + w1[c,1]*t4[l2,b,c],
//   t4[l,n,c] = sum_{j,k} x4[m,j,l,n+k-1] * w2[j,k,c],  l1=(p+13)%14, l2=(p+12)%14
// GEMM: rows r = l*14+n (196 -> 13 m16 tiles), cols c (256, two halves of 128),
//       K = kk = k*128+j (384 = 24 k16 steps), via mma.sync.m16n8k16 f16->f32.
// SMEM: xs[225][136] fp16 im2col source (row 224 = zeros for padded lanes),
//       Bs[128][392] fp16 = w2^T half (kk contiguous per c),
//       t4s[196][136] fp16 staging for the epilogue.
// ===========================================================================

__device__ __half g_Bh[256 * 384];   // w2^T fp16: [c][kk], kk = k*128+j

__device__ __forceinline__ uint32_t smem_u32(const void* p) {
    uint32_t a;
    asm("{ .reg .u64 t; cvta.to.shared.u64 t, %1; cvt.u32.u64 %0, t; }" : "=r"(a) : "l"(p));
    return a;
}

// ---------------------------------------------------------------------------
// kB: w2 (128,3,256) f32 -> g_Bh[c][k*128+j] fp16  (one-time, tiny)
// ---------------------------------------------------------------------------
__global__ __launch_bounds__(256) void kB(const float* __restrict__ w2) {
    int i = blockIdx.x * 256 + threadIdx.x;          // 98304 total
    if (i >= 98304) return;
    int c  = i / 384;
    int kk = i - c * 384;
    int k  = kk >> 7;
    int j  = kk & 127;
    g_Bh[i] = __float2half(w2[j * 768 + k * 256 + c]);
}

// ---------------------------------------------------------------------------
// kMain
// ---------------------------------------------------------------------------
static constexpr int XS_STRIDE = 136;   // halves; 68 words -> 4*row bank pattern
static constexpr int BS_STRIDE = 392;   // halves; 196 words -> 4*n bank pattern
static constexpr int T4_STRIDE = 136;

static constexpr int XS_OFF = 0;                       // 225*136*2 = 61200 B
static constexpr int BS_OFF = 61312;                   // 128*392*2 = 100352 B
static constexpr int T4_OFF = 161664;                  // 196*136*2 = 53312 B
static constexpr int SMEM_BYTES = 214976;

__global__ __launch_bounds__(1024, 1) void kMain(const float* __restrict__ x,
                                                 const float* __restrict__ w1,
                                                 float* __restrict__ out) {
    extern __shared__ char smem[];
    __half* xs  = (__half*)(smem + XS_OFF);
    __half* Bs  = (__half*)(smem + BS_OFF);
    __half* t4s = (__half*)(smem + T4_OFF);

    const int tid  = threadIdx.x;
    const int m    = blockIdx.x;
    const int wid  = tid >> 5;
    const int lane = tid & 31;

    // ---- zero xs (covers h-pads and the dummy zero row 224) ----
    uint32_t* xz = (uint32_t*)xs;
    for (int i = tid; i < 225 * XS_STRIDE / 2; i += 1024) xz[i] = 0;
    __syncthreads();

    // ---- build xs: xs[l*16 + h + 1][j] = fp16(x[m, j*196 + l*14 + h]) ----
    const float* xm = x + (size_t)m * 25088;
    for (int i = tid; i < 25088; i += 1024) {
        int j  = i / 196;
        int lh = i - j * 196;
        int l  = lh / 14;
        int h  = lh - l * 14;
        xs[(l * 16 + h + 1) * XS_STRIDE + j] = __float2half(xm[i]);
    }

    // ---- per-warp GEMM task: 26 active warps = 13 m-tiles x 2 n-groups ----
    const int  task   = wid;
    const bool active = task < 26;
    const int  mt     = active ? (task % 13) : 0;
    const int  ngrp   = active ? (task / 13) : 0;   // n-group: cols [ngrp*64, +64)
    const int  cbase  = ngrp * 8;                   // first n8-tile index

    // A-fragment ldmatrix lane addressing (row = lane&15, j-half = lane>>4)
    const int  rsel   = lane & 15;
    const int  r_row  = mt * 16 + rsel;
    const bool rvalid = r_row < 196;
    const int  base_lh = rvalid ? (r_row + 2 * (r_row / 14)) : 224; // l*16+n
    const int  j0pre   = (lane >> 4) << 3;          // 0 or 8
    const uint32_t xs_base = smem_u32(xs);
    const uint32_t bs_base = smem_u32(Bs);

    const int brow = lane >> 2;                     // 0..7 (n within n8 tile)
    const int bcol = (lane & 3) * 2;                // kk pair base

    float* om = out + (size_t)m * 50176;

    for (int hc = 0; hc < 2; hc++) {
        // ---- load B half: Bs[c][kk] <- g_Bh[hc*128 + c][kk] ----
        {
            const uint32_t* src = (const uint32_t*)(g_Bh + hc * 128 * 384);
            for (int i = tid; i < 128 * 192; i += 1024) {
                int c  = i / 192;
                int kw = i - c * 192;
                *(uint32_t*)(Bs + c * BS_STRIDE + kw * 2) = src[i];
            }
        }
        __syncthreads();

        float d[8][4];
        #pragma unroll
        for (int i = 0; i < 8; i++)
            #pragma unroll
            for (int q = 0; q < 4; q++) d[i][q] = 0.f;

        if (active) {
            #pragma unroll 2
            for (int s = 0; s < 24; s++) {
                const int tap = s >> 3;
                const int lh  = rvalid ? (base_lh + tap) : 224;
                uint32_t a_addr = xs_base +
                    (uint32_t)((lh * XS_STRIDE + (s & 7) * 16 + j0pre) * 2);
                uint32_t a0, a1, a2, a3;
                asm volatile("ldmatrix.sync.aligned.m8n8.x4.shared.b16 "
                             "{%0,%1,%2,%3}, [%4];"
                             : "=r"(a0), "=r"(a1), "=r"(a2), "=r"(a3) : "r"(a_addr));
                #pragma unroll
                for (int i = 0; i < 8; i++) {
                    int n_local = (cbase + i) * 8 + brow;
                    uint32_t b_addr = bs_base +
                        (uint32_t)((n_local * BS_STRIDE + s * 16 + bcol) * 2);
                    uint32_t b0, b1;
                    asm volatile("ld.shared.b32 %0, [%1];" : "=r"(b0) : "r"(b_addr));
                    asm volatile("ld.shared.b32 %0, [%1];" : "=r"(b1) : "r"(b_addr + 16));
                    asm volatile("mma.sync.aligned.m16n8k16.row.col.f32.f16.f16.f32 "
                                 "{%0,%1,%2,%3}, {%4,%5,%6,%7}, {%8,%9}, {%0,%1,%2,%3};"
                                 : "+f"(d[i][0]), "+f"(d[i][1]),
                                   "+f"(d[i][2]), "+f"(d[i][3])
                                 : "r"(a0), "r"(a1), "r"(a2), "r"(a3),
                                   "r"(b0), "r"(b1));
                }
            }
        }
        __syncthreads();   // GEMM reads of Bs/xs done before t4s writes overlap epilogue

        // ---- store fragments to t4s (fp16) ----
        if (active) {
            const int r0 = mt * 16 + (lane >> 2);
            #pragma unroll
            for (int i = 0; i < 8; i++) {
                const int c0 = (cbase + i) * 8 + (lane & 3) * 2;
                if (r0 < 196)
                    *(__half2*)(t4s + r0 * T4_STRIDE + c0) =
                        __floats2half2_rn(d[i][0], d[i][1]);
                if (r0 + 8 < 196)
                    *(__half2*)(t4s + (r0 + 8) * T4_STRIDE + c0) =
                        __floats2half2_rn(d[i][2], d[i][3]);
            }
        }
        __syncthreads();

        // ---- epilogue: two-tap combine over l, contiguous gmem writes ----
        const float2* w1v = (const float2*)w1;
        for (int i = tid; i < 25088; i += 1024) {
            int cl = i / 196;
            int rr = i - cl * 196;
            int p  = rr / 14;
            int b  = rr - p * 14;
            int l1 = (p == 0) ? 13 : p - 1;
            int l2 = (p < 2) ? p + 12 : p - 2;
            int c  = hc * 128 + cl;
            float2 wv = w1v[c];
            float v = wv.x * __half2float(t4s[(l1 * 14 + b) * T4_STRIDE + cl])
                    + wv.y * __half2float(t4s[(l2 * 14 + b) * T4_STRIDE + cl]);
            om[c * 196 + rr] = v;
        }
        __syncthreads();   // before Bs reload / t4s overwrite next half
    }
}

// ===========================================================================
extern "C" void kernel_launch(void* const* d_in, const int* in_sizes, int n_in,
                              void* d_out, int out_size) {
    const float* x  = (const float*)d_in[0];   // (1024, 1792, 14)
    const float* w1 = (const float*)d_in[1];   // (256, 2)
    const float* w2 = (const float*)d_in[2];   // (128, 3, 256)
    float* out = (float*)d_out;                // (1024, 256, 14, 14)

    static int attr_done = 0;
    if (!attr_done) {
        cudaFuncSetAttribute(kMain, cudaFuncAttributeMaxDynamicSharedMemorySize,
                             SMEM_BYTES);
        attr_done = 1;
    }

    kB<<<384, 256>>>(w2);
    kMain<<<1024, 1024, SMEM_BYTES>>>(x, w1, out);
}

// round 5
// speedup vs baseline: 5.2530x; 1.0211x over previous
#include <cuda_runtime.h>
#include <cuda_fp16.h>
#include <cstdint>

// ===========================================================================
// Fused kernel: one CTA per m.
//   out[m,c,p,b] = w1[c,0]*t4[l1,b,c] + w1[c,1]*t4[l2,b,c],
//   t4[l,n,c] = sum_{j,k} x4[m,j,l,n+k-1] * w2[j,k,c],  l1=(p+13)%14, l2=(p+12)%14
// GEMM: rows r = l*14+n (196 -> 13 m16 tiles), cols c (256, two halves of 128),
//       K = kk = k*128+j (384 = 24 k16 steps), mma.sync.m16n8k16 f16->f32.
// B operand fetched via ldmatrix.x4 (2 n8-tiles per ldmatrix), A via ldmatrix.x4.
// ===========================================================================

__device__ __half g_Bh[256 * 384];   // w2^T fp16: [c][kk], kk = k*128+j

__device__ __forceinline__ uint32_t smem_u32(const void* p) {
    uint32_t a;
    asm("{ .reg .u64 t; cvta.to.shared.u64 t, %1; cvt.u32.u64 %0, t; }" : "=r"(a) : "l"(p));
    return a;
}

// ---------------------------------------------------------------------------
// kB: w2 (128,3,256) f32 -> g_Bh[c][k*128+j] fp16  (one-time, tiny)
// ---------------------------------------------------------------------------
__global__ __launch_bounds__(256) void kB(const float* __restrict__ w2) {
    int i = blockIdx.x * 256 + threadIdx.x;          // 98304 total
    if (i >= 98304) return;
    int c  = i / 384;
    int kk = i - c * 384;
    int k  = kk >> 7;
    int j  = kk & 127;
    g_Bh[i] = __float2half(w2[j * 768 + k * 256 + c]);
}

// ---------------------------------------------------------------------------
// kMain
// ---------------------------------------------------------------------------
static constexpr int XS_STRIDE = 136;   // halves; 272 B rows -> conflict-free ldmatrix
static constexpr int BS_STRIDE = 392;   // halves; 784 B rows -> conflict-free ldmatrix
static constexpr int T4_STRIDE = 136;

static constexpr int XS_OFF = 0;                       // 225*136*2 = 61200 B
static constexpr int BS_OFF = 61312;                   // 128*392*2 = 100352 B
static constexpr int T4_OFF = 161664;                  // 196*136*2 = 53312 B
static constexpr int SMEM_BYTES = 214976;

__global__ __launch_bounds__(1024, 1) void kMain(const float* __restrict__ x,
                                                 const float* __restrict__ w1,
                                                 float* __restrict__ out) {
    extern __shared__ char smem[];
    __half* xs  = (__half*)(smem + XS_OFF);
    __half* Bs  = (__half*)(smem + BS_OFF);
    __half* t4s = (__half*)(smem + T4_OFF);

    const int tid  = threadIdx.x;
    const int m    = blockIdx.x;
    const int wid  = tid >> 5;
    const int lane = tid & 31;

    // ---- zero xs (covers h-pads; rows >=222 also used as junk rows for idle lanes) ----
    uint32_t* xz = (uint32_t*)xs;
    for (int i = tid; i < 225 * XS_STRIDE / 2; i += 1024) xz[i] = 0;
    __syncthreads();

    // ---- build xs: xs[l*16 + h + 1][j] = fp16(x[m, j*196 + l*14 + h]) ----
    const float* xm = x + (size_t)m * 25088;
    for (int i = tid; i < 25088; i += 1024) {
        int j  = i / 196;
        int lh = i - j * 196;
        int l  = lh / 14;
        int h  = lh - l * 14;
        xs[(l * 16 + h + 1) * XS_STRIDE + j] = __float2half(xm[i]);
    }

    // ---- per-warp GEMM task: 26 active warps = 13 m-tiles x 2 n64-groups ----
    const int  task   = wid;
    const bool active = task < 26;
    const int  mt     = active ? (task % 13) : 0;
    const int  ngrp   = active ? (task / 13) : 0;
    const int  cbase  = ngrp * 8;                   // first n8-tile index

    // A ldmatrix addressing: lanes 0-15 -> rows (m0,m1), 16-31 -> same rows cols+8
    const int  rsel    = lane & 15;
    const int  r_row   = mt * 16 + rsel;
    const bool rvalid  = r_row < 196;
    const int  base_lh = rvalid ? (r_row + 2 * (r_row / 14)) : 222; // junk rows 222..224 ok
    const int  j0pre   = (lane >> 4) << 3;
    const uint32_t xs_base = smem_u32(xs);
    const uint32_t a_pre   = xs_base + (uint32_t)((base_lh * XS_STRIDE + j0pre) * 2);

    // B ldmatrix addressing: matrix mi = lane>>3;
    //   n_in16 = ((mi>>1)&1)*8 + (lane&7), k_half = (mi&1)*8
    const int n_in16 = (((lane >> 4) & 1) << 3) + (lane & 7);
    const int k_half = ((lane >> 3) & 1) << 3;
    const uint32_t bs_base = smem_u32(Bs);
    const uint32_t b_pre   = bs_base +
        (uint32_t)(((cbase * 8 + n_in16) * BS_STRIDE + k_half) * 2);

    float* om = out + (size_t)m * 50176;

    for (int hc = 0; hc < 2; hc++) {
        // ---- load B half: Bs[c][kk] <- g_Bh[hc*128 + c][kk] ----
        {
            const uint32_t* src = (const uint32_t*)(g_Bh + hc * 128 * 384);
            for (int i = tid; i < 128 * 192; i += 1024) {
                int c  = i / 192;
                int kw = i - c * 192;
                *(uint32_t*)(Bs + c * BS_STRIDE + kw * 2) = src[i];
            }
        }
        __syncthreads();

        float d[8][4];
        #pragma unroll
        for (int i = 0; i < 8; i++)
            #pragma unroll
            for (int q = 0; q < 4; q++) d[i][q] = 0.f;

        if (active) {
            #pragma unroll 4
            for (int s = 0; s < 24; s++) {
                const int tap = s >> 3;
                uint32_t a_addr = a_pre + (uint32_t)(tap * (XS_STRIDE * 2)
                                                    + (s & 7) * 32);
                uint32_t a0, a1, a2, a3;
                asm volatile("ldmatrix.sync.aligned.m8n8.x4.shared.b16 "
                             "{%0,%1,%2,%3}, [%4];"
                             : "=r"(a0), "=r"(a1), "=r"(a2), "=r"(a3) : "r"(a_addr));
                uint32_t b_addr = b_pre + (uint32_t)(s * 32);
                #pragma unroll
                for (int q = 0; q < 4; q++) {
                    uint32_t b0, b1, b2, b3;
                    asm volatile("ldmatrix.sync.aligned.m8n8.x4.shared.b16 "
                                 "{%0,%1,%2,%3}, [%4];"
                                 : "=r"(b0), "=r"(b1), "=r"(b2), "=r"(b3)
                                 : "r"(b_addr));
                    b_addr += 16u * BS_STRIDE * 2u;   // next pair of n8-tiles
                    asm volatile("mma.sync.aligned.m16n8k16.row.col.f32.f16.f16.f32 "
                                 "{%0,%1,%2,%3}, {%4,%5,%6,%7}, {%8,%9}, {%0,%1,%2,%3};"
                                 : "+f"(d[2*q][0]), "+f"(d[2*q][1]),
                                   "+f"(d[2*q][2]), "+f"(d[2*q][3])
                                 : "r"(a0), "r"(a1), "r"(a2), "r"(a3),
                                   "r"(b0), "r"(b1));
                    asm volatile("mma.sync.aligned.m16n8k16.row.col.f32.f16.f16.f32 "
                                 "{%0,%1,%2,%3}, {%4,%5,%6,%7}, {%8,%9}, {%0,%1,%2,%3};"
                                 : "+f"(d[2*q+1][0]), "+f"(d[2*q+1][1]),
                                   "+f"(d[2*q+1][2]), "+f"(d[2*q+1][3])
                                 : "r"(a0), "r"(a1), "r"(a2), "r"(a3),
                                   "r"(b2), "r"(b3));
                }
            }
        }
        __syncthreads();   // GEMM reads of Bs/xs done before t4s writes

        // ---- store fragments to t4s (fp16) ----
        if (active) {
            const int r0 = mt * 16 + (lane >> 2);
            #pragma unroll
            for (int i = 0; i < 8; i++) {
                const int c0 = (cbase + i) * 8 + (lane & 3) * 2;
                if (r0 < 196)
                    *(__half2*)(t4s + r0 * T4_STRIDE + c0) =
                        __floats2half2_rn(d[i][0], d[i][1]);
                if (r0 + 8 < 196)
                    *(__half2*)(t4s + (r0 + 8) * T4_STRIDE + c0) =
                        __floats2half2_rn(d[i][2], d[i][3]);
            }
        }
        __syncthreads();

        // ---- epilogue: two-tap combine over l, contiguous gmem writes ----
        const float2* w1v = (const float2*)w1;
        for (int i = tid; i < 25088; i += 1024) {
            int cl = i / 196;
            int rr = i - cl * 196;
            int p  = rr / 14;
            int b  = rr - p * 14;
            int l1 = (p == 0) ? 13 : p - 1;
            int l2 = (p < 2) ? p + 12 : p - 2;
            int c  = hc * 128 + cl;
            float2 wv = w1v[c];
            float v = wv.x * __half2float(t4s[(l1 * 14 + b) * T4_STRIDE + cl])
                    + wv.y * __half2float(t4s[(l2 * 14 + b) * T4_STRIDE + cl]);
            om[c * 196 + rr] = v;
        }
        __syncthreads();   // before Bs reload / t4s overwrite next half
    }
}

// ===========================================================================
extern "C" void kernel_launch(void* const* d_in, const int* in_sizes, int n_in,
                              void* d_out, int out_size) {
    const float* x  = (const float*)d_in[0];   // (1024, 1792, 14)
    const float* w1 = (const float*)d_in[1];   // (256, 2)
    const float* w2 = (const float*)d_in[2];   // (128, 3, 256)
    float* out = (float*)d_out;                // (1024, 256, 14, 14)

    static int attr_done = 0;
    if (!attr_done) {
        cudaFuncSetAttribute(kMain, cudaFuncAttributeMaxDynamicSharedMemorySize,
                             SMEM_BYTES);
        attr_done = 1;
    }

    kB<<<384, 256>>>(w2);
    kMain<<<1024, 1024, SMEM_BYTES>>>(x, w1, out);
}